// round 14
// baseline (speedup 1.0000x reference)
#include <cuda_runtime.h>
#include <cuda_bf16.h>
#include <math.h>

#define S 128
#define B 1024
#define T 96
#define E 64
#define H 200
#define HH 100
#define ATT 200
#define DEC_IN 440
#define XCAT 640
#define P2B 8

// ---------------- scratch (device globals; no allocations allowed) -------------
__device__ float g_xw_f[S * B * 400];
__device__ float g_xw_b[S * B * 400];
__device__ __nv_bfloat16 g_enc16[B * S * H];   // [B, S, 200] bf16
__device__ float g_hfin[2 * B * HH];
__device__ float g_cf[B * HH];
__device__ float g_cb[B * HH];
__device__ float g_Wcat[800 * XCAT];     // gate-interleaved rows r=4j+g
__device__ float g_bcat[800];
__device__ float g_WattnT[H * H];        // W_attn transposed: [k][j]
__device__ float g_WavT[400 * 200];      // W_av transposed:   [k][n]
__device__ float g_h[B * H];
__device__ float g_c[B * H];
__device__ float g_Hbuf[T * B * H];
__device__ float g_xcat[B * XCAT];

__device__ __forceinline__ float sigf(float x) { return 1.f / (1.f + expf(-x)); }

// ============ decoder z-GEMM+cell: 128 threads, BM=64, BN=32 (R11-proven) =======
__global__ void __launch_bounds__(128) k_zcell(int t)
{
    cudaGridDependencySynchronize();   // PDL
    __shared__ float As[16][64];
    __shared__ float Ws[16][32];
    const int bm = blockIdx.y * 64, bn = blockIdx.x * 32;
    const int tid = threadIdx.x;
    const int ty = tid >> 3, tx = tid & 7;
    const int N = 800, K = XCAT;

    float4 pfA[2];
    float4 pfW;
    {
#pragma unroll
        for (int i = 0; i < 2; i++) {
            int f = tid + i * 128;
            int m = f >> 2, kc = f & 3;
            pfA[i] = *(const float4*)(g_xcat + (size_t)(bm + m) * K + kc * 4);
        }
        int n = bn + (tid >> 2), k = (tid & 3) * 4;
        pfW = (n < N) ? *(const float4*)(g_Wcat + (size_t)n * K + k)
                      : make_float4(0.f, 0.f, 0.f, 0.f);
    }

    unsigned long long acc[2][4];
#pragma unroll
    for (int p = 0; p < 2; p++)
#pragma unroll
        for (int j = 0; j < 4; j++) acc[p][j] = 0ull;

    for (int kt = 0; kt < 40; kt++) {
#pragma unroll
        for (int i = 0; i < 2; i++) {
            int f = tid + i * 128;
            int m = f >> 2, kc = f & 3;
            As[kc*4+0][m] = pfA[i].x; As[kc*4+1][m] = pfA[i].y;
            As[kc*4+2][m] = pfA[i].z; As[kc*4+3][m] = pfA[i].w;
        }
        { int n = tid >> 2, kc = tid & 3;
          Ws[kc*4+0][n] = pfW.x; Ws[kc*4+1][n] = pfW.y;
          Ws[kc*4+2][n] = pfW.z; Ws[kc*4+3][n] = pfW.w; }
        __syncthreads();

        if (kt + 1 < 40) {
            int k0 = (kt + 1) * 16;
#pragma unroll
            for (int i = 0; i < 2; i++) {
                int f = tid + i * 128;
                int m = f >> 2, kc = f & 3;
                pfA[i] = *(const float4*)(g_xcat + (size_t)(bm + m) * K + k0 + kc * 4);
            }
            int n = bn + (tid >> 2), k = k0 + (tid & 3) * 4;
            pfW = (n < N) ? *(const float4*)(g_Wcat + (size_t)n * K + k)
                          : make_float4(0.f, 0.f, 0.f, 0.f);
        }

#pragma unroll
        for (int kk = 0; kk < 16; kk++) {
            unsigned long long a2[2];
            const unsigned long long* pa =
                (const unsigned long long*)&As[kk][ty * 4];
            a2[0] = pa[0]; a2[1] = pa[1];
            float4 wv = *(const float4*)&Ws[kk][tx * 4];
            unsigned long long w2[4];
            asm("mov.b64 %0, {%1, %2};" : "=l"(w2[0]) : "f"(wv.x), "f"(wv.x));
            asm("mov.b64 %0, {%1, %2};" : "=l"(w2[1]) : "f"(wv.y), "f"(wv.y));
            asm("mov.b64 %0, {%1, %2};" : "=l"(w2[2]) : "f"(wv.z), "f"(wv.z));
            asm("mov.b64 %0, {%1, %2};" : "=l"(w2[3]) : "f"(wv.w), "f"(wv.w));
#pragma unroll
            for (int p = 0; p < 2; p++)
#pragma unroll
                for (int j = 0; j < 4; j++)
                    asm("fma.rn.f32x2 %0, %1, %2, %0;"
                        : "+l"(acc[p][j]) : "l"(a2[p]), "l"(w2[j]));
        }
        __syncthreads();
    }

    int n0 = bn + tx * 4;
    if (n0 >= N) return;
    int j = n0 >> 2;
    float bz[4];
#pragma unroll
    for (int g = 0; g < 4; g++) bz[g] = g_bcat[n0 + g];
#pragma unroll
    for (int p = 0; p < 2; p++) {
        int m0 = bm + ty * 4 + 2 * p;
        float zl[4], zh[4];
#pragma unroll
        for (int g = 0; g < 4; g++) {
            float lo, hi;
            asm("mov.b64 {%0, %1}, %2;" : "=f"(lo), "=f"(hi) : "l"(acc[p][g]));
            zl[g] = lo + bz[g];
            zh[g] = hi + bz[g];
        }
#pragma unroll
        for (int r = 0; r < 2; r++) {
            int m = m0 + r;
            float zi = r ? zh[0] : zl[0];
            float zf = r ? zh[1] : zl[1];
            float zg = r ? zh[2] : zl[2];
            float zo = r ? zh[3] : zl[3];
            float c = g_c[m * H + j];
            float cn = sigf(zf) * c + sigf(zi) * tanhf(zg);
            float hn = sigf(zo) * tanhf(cn);
            g_c[m * H + j] = cn;
            g_h[m * H + j] = hn;
            g_Hbuf[((size_t)t * B + m) * H + j] = hn;
        }
    }
}

// ============ fused P2: gtil + attention + out-GEMM + xcat(t+1) =================
// 128 blocks x 8 batch rows x 256 threads. Weights streamed once per 8 rows.
// Attention: ONE WARP PER ROW, register-resident online softmax, no per-row syncs.
__global__ void __launch_bounds__(256) k_p2(
    int t, const int* __restrict__ is_prod, const int* __restrict__ prod_ids,
    const int* __restrict__ prim_ids, const int* __restrict__ field_ids,
    const int* __restrict__ parent_t,
    const float* __restrict__ actprod, const float* __restrict__ prim,
    const float* __restrict__ field, float* __restrict__ out)
{
    __shared__ float sh[P2B * H];       // h rows
    __shared__ float sgt[P2B * H];      // gtil rows
    __shared__ float scth[P2B * 2 * H]; // [ctx | h] rows
    cudaGridDependencySynchronize();    // PDL: wait for zcell
    const int tid = threadIdx.x;
    const int warp = tid >> 5, lane = tid & 31;
    const int b0 = blockIdx.x * P2B;

    // 1) load h (g_h rows for b0..b0+7 are one contiguous range)
    {
        const float4* src = (const float4*)(g_h + (size_t)b0 * H);
        float4* dst = (float4*)sh;
        for (int i = tid; i < P2B * H / 4; i += 256) dst[i] = src[i];
    }
    __syncthreads();

    // 2) batched gtil = h @ W_attn  (stream WattnT once per block; smem broadcast)
    if (tid < H) {
        float acc[P2B] = {0.f, 0.f, 0.f, 0.f, 0.f, 0.f, 0.f, 0.f};
#pragma unroll 2
        for (int k = 0; k < H; k++) {
            float w = g_WattnT[k * H + tid];
#pragma unroll
            for (int bb = 0; bb < P2B; bb++)
                acc[bb] = fmaf(sh[bb * H + k], w, acc[bb]);
        }
#pragma unroll
        for (int bb = 0; bb < P2B; bb++) sgt[bb * H + tid] = acc[bb];
    }
    __syncthreads();

    // 3) attention: warp `warp` owns row b0+warp; full-S online softmax in regs
    {
        const int bb = warp;
        float sgr[8];
#pragma unroll
        for (int i = 0; i < 4; i++) {
            int k2 = lane + 32 * i;
            sgr[2*i]   = (k2 < 100) ? sgt[bb * H + 2*k2]   : 0.f;
            sgr[2*i+1] = (k2 < 100) ? sgt[bb * H + 2*k2+1] : 0.f;
        }
        float m = -1e30f, zs = 0.f;
        float ctx[8] = {0.f, 0.f, 0.f, 0.f, 0.f, 0.f, 0.f, 0.f};
        const __nv_bfloat162* eb =
            (const __nv_bfloat162*)(g_enc16 + (size_t)(b0 + bb) * S * H);
#pragma unroll 2
        for (int s = 0; s < S; s++) {
            const __nv_bfloat162* er = eb + s * 100;
            float v[8];
#pragma unroll
            for (int i = 0; i < 4; i++) {
                int k2 = lane + 32 * i;
                if (k2 < 100) {
                    float2 p = __bfloat1622float2(er[k2]);
                    v[2*i] = p.x; v[2*i+1] = p.y;
                } else { v[2*i] = 0.f; v[2*i+1] = 0.f; }
            }
            float sc = 0.f;
#pragma unroll
            for (int i = 0; i < 8; i++) sc += v[i] * sgr[i];
#pragma unroll
            for (int o = 16; o; o >>= 1) sc += __shfl_xor_sync(0xffffffffu, sc, o);
            float mn = fmaxf(m, sc);
            float corr = expf(m - mn);
            float e = expf(sc - mn);
            zs = zs * corr + e;
#pragma unroll
            for (int i = 0; i < 8; i++) ctx[i] = ctx[i] * corr + e * v[i];
            m = mn;
        }
        float invZ = 1.f / zs;
#pragma unroll
        for (int i = 0; i < 4; i++) {
            int k2 = lane + 32 * i;
            if (k2 < 100) {
                scth[bb * 2 * H + 2*k2]   = ctx[2*i]   * invZ;
                scth[bb * 2 * H + 2*k2+1] = ctx[2*i+1] * invZ;
            }
        }
        for (int j = lane; j < H; j += 32)
            scth[bb * 2 * H + H + j] = sh[bb * H + j];
    }
    __syncthreads();

    // 4) batched s_att = tanh(cath @ W_av^T); write out[t] + xcat s_att cols
    if (tid < H) {
        float acc[P2B] = {0.f, 0.f, 0.f, 0.f, 0.f, 0.f, 0.f, 0.f};
#pragma unroll 2
        for (int k = 0; k < 2 * H; k++) {
            float w = g_WavT[k * H + tid];
#pragma unroll
            for (int bb = 0; bb < P2B; bb++)
                acc[bb] = fmaf(scth[bb * 2 * H + k], w, acc[bb]);
        }
#pragma unroll
        for (int bb = 0; bb < P2B; bb++) {
            float v = tanhf(acc[bb]);
            out[((size_t)t * B + b0 + bb) * ATT + tid] = v;
            if (t + 1 < T)
                g_xcat[(size_t)(b0 + bb) * XCAT + 32 + tid] = v;
        }
    }

    // 5) xcat(t+1): remaining columns for all 8 rows
    if (t + 1 < T) {
        int t1 = t + 1;
        for (int i = tid; i < P2B * 440; i += 256) {
            int bb = i / 440, cc = i - bb * 440;
            int b = b0 + bb;
            int col;
            float v;
            if (cc < 32) {
                col = cc;
                int idx = t1 * B + b;
                v = (is_prod[idx] == 1) ? actprod[prod_ids[idx] * 32 + cc]
                                        : prim[prim_ids[idx] * 32 + cc];
            } else if (cc < 40) {
                col = 232 + (cc - 32);
                v = field[field_ids[t1 * B + b] * 8 + (cc - 32)];
            } else if (cc < 240) {
                int j = cc - 40;
                col = 240 + j;
                int pt = parent_t[t1 * B + b];
                v = g_Hbuf[((size_t)pt * B + b) * H + j];
            } else {
                int j = cc - 240;
                col = DEC_IN + j;
                v = sh[bb * H + j];
            }
            g_xcat[(size_t)b * XCAT + col] = v;
        }
    }
}

// ========== xw GEMM with fused embedding gather (prologue; R7-proven) ===========
__global__ void __launch_bounds__(256) k_xw(
    const int* __restrict__ sent, const float* __restrict__ src_emb,
    const float* __restrict__ Wf, const float* __restrict__ bf,
    const float* __restrict__ Wb, const float* __restrict__ bb)
{
    __shared__ float As[16][128];
    __shared__ float Ws[16][64];
    const int bm = blockIdx.y * 128, bn = blockIdx.x * 64;
    const float* W = blockIdx.z ? Wb : Wf;
    const float* bias = blockIdx.z ? bb : bf;
    float* C = blockIdx.z ? g_xw_b : g_xw_f;
    const int tid = threadIdx.x;
    const int ty = tid >> 4, tx = tid & 15;

    int sidx[2];
#pragma unroll
    for (int i = 0; i < 2; i++) {
        int f = tid + i * 256;
        sidx[i] = sent[bm + (f >> 2)];
    }

    float4 pfA[2], pfW;
#pragma unroll
    for (int i = 0; i < 2; i++) {
        int f = tid + i * 256;
        pfA[i] = *(const float4*)(src_emb + (size_t)sidx[i] * E + (f & 3) * 4);
    }
    {
        int n = bn + (tid >> 2), k = (tid & 3) * 4;
        pfW = (n < 400) ? *(const float4*)(W + (size_t)n * E + k)
                        : make_float4(0.f, 0.f, 0.f, 0.f);
    }

    unsigned long long acc[4][4];
#pragma unroll
    for (int p = 0; p < 4; p++)
#pragma unroll
        for (int j = 0; j < 4; j++) acc[p][j] = 0ull;

    for (int kt = 0; kt < 4; kt++) {
#pragma unroll
        for (int i = 0; i < 2; i++) {
            int f = tid + i * 256;
            int m = f >> 2, kc = f & 3;
            As[kc*4+0][m] = pfA[i].x; As[kc*4+1][m] = pfA[i].y;
            As[kc*4+2][m] = pfA[i].z; As[kc*4+3][m] = pfA[i].w;
        }
        { int n = tid >> 2, kc = tid & 3;
          Ws[kc*4+0][n] = pfW.x; Ws[kc*4+1][n] = pfW.y;
          Ws[kc*4+2][n] = pfW.z; Ws[kc*4+3][n] = pfW.w; }
        __syncthreads();

        if (kt + 1 < 4) {
            int k0 = (kt + 1) * 16;
#pragma unroll
            for (int i = 0; i < 2; i++) {
                int f = tid + i * 256;
                pfA[i] = *(const float4*)(src_emb + (size_t)sidx[i] * E + k0 + (f & 3) * 4);
            }
            int n = bn + (tid >> 2), k = k0 + (tid & 3) * 4;
            pfW = (n < 400) ? *(const float4*)(W + (size_t)n * E + k)
                            : make_float4(0.f, 0.f, 0.f, 0.f);
        }

#pragma unroll
        for (int kk = 0; kk < 16; kk++) {
            unsigned long long a2[4];
            const unsigned long long* pa = (const unsigned long long*)&As[kk][ty * 8];
#pragma unroll
            for (int p = 0; p < 4; p++) a2[p] = pa[p];
            float4 wv = *(const float4*)&Ws[kk][tx * 4];
            unsigned long long w2[4];
            asm("mov.b64 %0, {%1, %2};" : "=l"(w2[0]) : "f"(wv.x), "f"(wv.x));
            asm("mov.b64 %0, {%1, %2};" : "=l"(w2[1]) : "f"(wv.y), "f"(wv.y));
            asm("mov.b64 %0, {%1, %2};" : "=l"(w2[2]) : "f"(wv.z), "f"(wv.z));
            asm("mov.b64 %0, {%1, %2};" : "=l"(w2[3]) : "f"(wv.w), "f"(wv.w));
#pragma unroll
            for (int p = 0; p < 4; p++)
#pragma unroll
                for (int j = 0; j < 4; j++)
                    asm("fma.rn.f32x2 %0, %1, %2, %0;"
                        : "+l"(acc[p][j]) : "l"(a2[p]), "l"(w2[j]));
        }
        __syncthreads();
    }

    float bv[4];
#pragma unroll
    for (int j = 0; j < 4; j++) {
        int n = bn + tx * 4 + j;
        bv[j] = (n < 400) ? bias[n] : 0.f;
    }
#pragma unroll
    for (int p = 0; p < 4; p++) {
        int m0 = bm + ty * 8 + 2 * p;
#pragma unroll
        for (int j = 0; j < 4; j++) {
            int n = bn + tx * 4 + j;
            if (n >= 400) continue;
            float lo, hi;
            asm("mov.b64 {%0, %1}, %2;" : "=f"(lo), "=f"(hi) : "l"(acc[p][j]));
            C[(size_t)m0 * 400 + n] = lo + bv[j];
            C[(size_t)(m0 + 1) * 400 + n] = hi + bv[j];
        }
    }
}

// ---------------- fused bidirectional LSTM encoder (writes bf16 enc) ------------
#define ENC_BPB 14
#define ENC_SMEM_FLOATS (40000 + ENC_BPB * HH + ENC_BPB * 4 * HH)
__global__ void __launch_bounds__(256) k_encoder(const float* __restrict__ Whh_f,
                                                 const float* __restrict__ Whh_b)
{
    extern __shared__ float sm[];
    float* sW = sm;
    float* sh = sm + 40000;
    float* sz = sm + 40000 + ENC_BPB * HH;

    int dir = blockIdx.x >= 74;
    int lg = dir ? blockIdx.x - 74 : blockIdx.x;
    const float* Whh = dir ? Whh_b : Whh_f;
    const float* xw = dir ? g_xw_b : g_xw_f;
    float* cg = dir ? g_cb : g_cf;
    int b0 = lg * ENC_BPB;
    int nb = min(ENC_BPB, B - b0);
    int tid = threadIdx.x;

    for (int i = tid; i < 40000; i += 256) sW[i] = Whh[i];
    for (int i = tid; i < ENC_BPB * HH; i += 256) sh[i] = 0.f;
    float creg[6] = {0.f, 0.f, 0.f, 0.f, 0.f, 0.f};
    __syncthreads();

    for (int t = 0; t < S; t++) {
        int tt = dir ? (S - 1 - t) : t;
        if (tid < 200) {
            int jg = tid % 100;
            int bgb = (tid / 100) * 7;
            float acc[4][7];
#pragma unroll
            for (int r = 0; r < 4; r++)
#pragma unroll
                for (int bb = 0; bb < 7; bb++) {
                    int bl = bgb + bb;
                    acc[r][bb] = (bl < nb)
                        ? xw[((size_t)tt * B + (b0 + bl)) * 400 + 4 * jg + r] : 0.f;
                }
            const float4* shv = (const float4*)sh;
            const float4* swv = (const float4*)sW;
            for (int k4 = 0; k4 < 25; k4++) {
                float4 w0 = swv[(4 * jg + 0) * 25 + k4];
                float4 w1 = swv[(4 * jg + 1) * 25 + k4];
                float4 w2 = swv[(4 * jg + 2) * 25 + k4];
                float4 w3 = swv[(4 * jg + 3) * 25 + k4];
#pragma unroll
                for (int bb = 0; bb < 7; bb++) {
                    float4 hv = shv[(bgb + bb) * 25 + k4];
                    acc[0][bb] += w0.x * hv.x + w0.y * hv.y + w0.z * hv.z + w0.w * hv.w;
                    acc[1][bb] += w1.x * hv.x + w1.y * hv.y + w1.z * hv.z + w1.w * hv.w;
                    acc[2][bb] += w2.x * hv.x + w2.y * hv.y + w2.z * hv.z + w2.w * hv.w;
                    acc[3][bb] += w3.x * hv.x + w3.y * hv.y + w3.z * hv.z + w3.w * hv.w;
                }
            }
#pragma unroll
            for (int r = 0; r < 4; r++)
#pragma unroll
                for (int bb = 0; bb < 7; bb++)
                    if (bgb + bb < nb) sz[(bgb + bb) * 400 + 4 * jg + r] = acc[r][bb];
        }
        __syncthreads();
#pragma unroll
        for (int i = 0; i < 6; i++) {
            int pp = tid + i * 256;
            if (pp < nb * HH) {
                int bl = pp / HH, j = pp % HH;
                float zi = sz[bl * 400 + j];
                float zf = sz[bl * 400 + 100 + j];
                float zg = sz[bl * 400 + 200 + j];
                float zo = sz[bl * 400 + 300 + j];
                float cn = sigf(zf) * creg[i] + sigf(zi) * tanhf(zg);
                float hn = sigf(zo) * tanhf(cn);
                creg[i] = cn;
                sh[bl * HH + j] = hn;
                g_enc16[((size_t)(b0 + bl) * S + tt) * H + dir * HH + j] =
                    __float2bfloat16(hn);
            }
        }
        __syncthreads();
    }
#pragma unroll
    for (int i = 0; i < 6; i++) {
        int pp = tid + i * 256;
        if (pp < nb * HH) {
            int bl = pp / HH, j = pp % HH;
            cg[(b0 + bl) * HH + j] = creg[i];
            g_hfin[dir * B * HH + (b0 + bl) * HH + j] = sh[bl * HH + j];
        }
    }
}

// ---------------- weight prep: Wcat + WattnT + WavT + bcat ----------------------
__global__ void k_prep(const float* __restrict__ Wih_d, const float* __restrict__ Whh_d,
                       const float* __restrict__ b_d, const float* __restrict__ W_attn,
                       const float* __restrict__ W_av) {
    int i = blockIdx.x * blockDim.x + threadIdx.x;
    if (i < 800 * XCAT) {
        int r = i / XCAT, k = i % XCAT;
        int src = (r & 3) * H + (r >> 2);
        g_Wcat[i] = (k < DEC_IN) ? Wih_d[src * DEC_IN + k]
                                 : Whh_d[src * H + (k - DEC_IN)];
        return;
    }
    int i2 = i - 800 * XCAT;
    if (i2 < H * H) {
        int k = i2 / H, j = i2 % H;
        g_WattnT[i2] = W_attn[j * H + k];
        return;
    }
    int i3 = i2 - H * H;
    if (i3 < 400 * 200) {
        int k = i3 / 200, n = i3 % 200;
        g_WavT[i3] = W_av[n * 400 + k];
        return;
    }
    int r = i3 - 400 * 200;
    if (r < 800) g_bcat[r] = b_d[(r & 3) * H + (r >> 2)];
}

// ---------------- decoder init: h0/c0 + initial xcat (inp=0 | h0) ---------------
__global__ void k_dec_init2() {
    int e = blockIdx.x * blockDim.x + threadIdx.x;
    if (e >= B * XCAT) return;
    int b = e / XCAT, col = e % XCAT;
    if (col < DEC_IN) { g_xcat[e] = 0.f; return; }
    int k = col - DEC_IN;
    int hi = (k >= HH) ? 1 : 0;
    int j = k - hi * HH;
    float hv, cv;
    if (b < 512) {
        int bb = 2 * b + hi;
        hv = g_hfin[bb * HH + j];
        cv = g_cf[bb * HH + j];
    } else {
        int bb = 2 * (b - 512) + hi;
        hv = g_hfin[B * HH + bb * HH + j];
        cv = g_cb[bb * HH + j];
    }
    g_h[b * H + k] = hv;
    g_c[b * H + k] = cv;
    g_xcat[e] = hv;
}

// ---------------- host launch ----------------
extern "C" void kernel_launch(void* const* d_in, const int* in_sizes, int n_in,
                              void* d_out, int out_size) {
    const int* sentences  = (const int*)d_in[0];
    const int* is_prod    = (const int*)d_in[1];
    const int* prod_ids   = (const int*)d_in[2];
    const int* prim_ids   = (const int*)d_in[3];
    const int* field_ids  = (const int*)d_in[4];
    const int* parent_t   = (const int*)d_in[5];
    const float* src_emb  = (const float*)d_in[6];
    const float* actprod_emb = (const float*)d_in[7];
    const float* prim_emb = (const float*)d_in[8];
    const float* field_emb = (const float*)d_in[9];
    const float* Wih_f = (const float*)d_in[10];
    const float* Whh_f = (const float*)d_in[11];
    const float* b_f   = (const float*)d_in[12];
    const float* Wih_b = (const float*)d_in[13];
    const float* Whh_b = (const float*)d_in[14];
    const float* b_b   = (const float*)d_in[15];
    const float* Wih_d = (const float*)d_in[16];
    const float* Whh_d = (const float*)d_in[17];
    const float* b_d   = (const float*)d_in[18];
    const float* W_attn = (const float*)d_in[19];
    const float* W_av   = (const float*)d_in[20];
    float* out = (float*)d_out;

    cudaFuncSetAttribute(k_encoder, cudaFuncAttributeMaxDynamicSharedMemorySize,
                         ENC_SMEM_FLOATS * 4);

    cudaLaunchAttribute at[1];
    at[0].id = cudaLaunchAttributeProgrammaticStreamSerialization;
    at[0].val.programmaticStreamSerializationAllowed = 1;

    // 1) xw projections with fused embedding gather (both directions)
    {
        dim3 g(7, (S * B) / 128, 2);
        k_xw<<<g, 256>>>(sentences, src_emb, Wih_f, b_f, Wih_b, b_b);
    }
    // 2) bidirectional encoder (writes bf16 g_enc16 directly)
    k_encoder<<<148, 256, ENC_SMEM_FLOATS * 4>>>(Whh_f, Whh_b);
    // 3) weight prep + decoder init
    k_prep<<<(800 * XCAT + H * H + 400 * 200 + 800 + 255) / 256, 256>>>(
        Wih_d, Whh_d, b_d, W_attn, W_av);
    k_dec_init2<<<(B * XCAT + 255) / 256, 256>>>();

    // 4) decoder loop: 2 PDL-chained nodes per step
    dim3 gz(25, 16);   // zcell: 400 blocks of 128 threads (R11-proven)
    for (int t = 0; t < T; t++) {
        {
            cudaLaunchConfig_t cfg = {};
            cfg.gridDim = gz; cfg.blockDim = dim3(128);
            cfg.attrs = at; cfg.numAttrs = 1;
            cudaLaunchKernelEx(&cfg, k_zcell, t);
        }
        {
            cudaLaunchConfig_t cfg = {};
            cfg.gridDim = dim3(B / P2B); cfg.blockDim = dim3(256);
            cfg.attrs = at; cfg.numAttrs = 1;
            cudaLaunchKernelEx(&cfg, k_p2, t, is_prod, prod_ids, prim_ids,
                               field_ids, parent_t, actprod_emb, prim_emb,
                               field_emb, out);
        }
    }
}

// round 15
// speedup vs baseline: 1.5402x; 1.5402x over previous
#include <cuda_runtime.h>
#include <cuda_bf16.h>
#include <math.h>

#define S 128
#define B 1024
#define T 96
#define E 64
#define H 200
#define HH 100
#define ATT 200
#define DEC_IN 440
#define XCAT 640

// ---------------- scratch (device globals; no allocations allowed) -------------
__device__ float g_xw_f[S * B * 400];
__device__ float g_xw_b[S * B * 400];
__device__ __nv_bfloat16 g_enc16[B * S * H];   // [B, S, 200] bf16
__device__ float g_hfin[2 * B * HH];
__device__ float g_cf[B * HH];
__device__ float g_cb[B * HH];
__device__ float g_Wcat[800 * XCAT];     // gate-interleaved rows r=4j+g
__device__ float g_bcat[800];
__device__ float g_WattnT[H * H];        // W_attn transposed
__device__ float g_h[B * H];
__device__ float g_c[B * H];
__device__ float g_Hbuf[T * B * H];
__device__ float g_xcat[B * XCAT];
__device__ float g_gtil[B * H];
__device__ float g_cath[B * 2 * H];

__device__ __forceinline__ float sigf(float x) { return 1.f / (1.f + expf(-x)); }

// ============ decoder GEMM: 128 threads, BM=64, BN=32, BK=16, double-buffered ===
// C[M,N] = A[M,K] @ W[N,K]^T. 16 outputs/thread (4m x 4n) -> 8 FFMA2/kk.
// 2-stage smem ping-pong: ONE __syncthreads per K-tile.
// MODE 0: C = A@W^T + bias
// MODE 1: v = tanh(A@W^T); C[m,n] = v; C2[m, 32+n] = v
// MODE 2: gate-interleaved z; LSTM cell in epilogue -> g_h, g_c, g_Hbuf[t].
template <int MODE>
__global__ void __launch_bounds__(128) k_gemm(
    const float* __restrict__ A, const float* __restrict__ W,
    const float* __restrict__ bias, float* __restrict__ C,
    float* __restrict__ C2, int M, int N, int K, int t)
{
    cudaGridDependencySynchronize();   // PDL
    __shared__ float As[2][16][64];
    __shared__ float Ws[2][16][32];
    const int bm = blockIdx.y * 64, bn = blockIdx.x * 32;
    const int tid = threadIdx.x;
    const int ty = tid >> 3, tx = tid & 7;
    const int KT = (K + 15) / 16;

    float4 pfA[2];
    float4 pfW;
    // ---- load tile 0 into registers ----
    {
#pragma unroll
        for (int i = 0; i < 2; i++) {
            int f = tid + i * 128;
            int m = f >> 2, kc = f & 3, k = kc * 4;
            float4 v = make_float4(0.f, 0.f, 0.f, 0.f);
            const float* ap = A + (size_t)(bm + m) * K + k;
            if (k + 3 < K) v = *(const float4*)ap;
            else { if (k < K) v.x = ap[0]; if (k+1 < K) v.y = ap[1];
                   if (k+2 < K) v.z = ap[2]; if (k+3 < K) v.w = ap[3]; }
            pfA[i] = v;
        }
        int n = bn + (tid >> 2), k = (tid & 3) * 4;
        float4 v = make_float4(0.f, 0.f, 0.f, 0.f);
        if (n < N) {
            const float* wp = W + (size_t)n * K + k;
            if (k + 3 < K) v = *(const float4*)wp;
            else { if (k < K) v.x = wp[0]; if (k+1 < K) v.y = wp[1];
                   if (k+2 < K) v.z = wp[2]; if (k+3 < K) v.w = wp[3]; }
        }
        pfW = v;
    }
    // ---- stage tile 0 into smem buffer 0 ----
    {
#pragma unroll
        for (int i = 0; i < 2; i++) {
            int f = tid + i * 128;
            int m = f >> 2, kc = f & 3;
            As[0][kc*4+0][m] = pfA[i].x; As[0][kc*4+1][m] = pfA[i].y;
            As[0][kc*4+2][m] = pfA[i].z; As[0][kc*4+3][m] = pfA[i].w;
        }
        int n = tid >> 2, kc = tid & 3;
        Ws[0][kc*4+0][n] = pfW.x; Ws[0][kc*4+1][n] = pfW.y;
        Ws[0][kc*4+2][n] = pfW.z; Ws[0][kc*4+3][n] = pfW.w;
    }
    __syncthreads();

    unsigned long long acc[2][4];
#pragma unroll
    for (int p = 0; p < 2; p++)
#pragma unroll
        for (int j = 0; j < 4; j++) acc[p][j] = 0ull;

    for (int kt = 0; kt < KT; kt++) {
        const int cur = kt & 1, nxt = cur ^ 1;
        const bool more = (kt + 1 < KT);

        // prefetch next tile from global (overlaps compute below)
        if (more) {
            int k0 = (kt + 1) * 16;
#pragma unroll
            for (int i = 0; i < 2; i++) {
                int f = tid + i * 128;
                int m = f >> 2, kc = f & 3, k = k0 + kc * 4;
                float4 v = make_float4(0.f, 0.f, 0.f, 0.f);
                const float* ap = A + (size_t)(bm + m) * K + k;
                if (k + 3 < K) v = *(const float4*)ap;
                else { if (k < K) v.x = ap[0]; if (k+1 < K) v.y = ap[1];
                       if (k+2 < K) v.z = ap[2]; if (k+3 < K) v.w = ap[3]; }
                pfA[i] = v;
            }
            int n = bn + (tid >> 2), k = k0 + (tid & 3) * 4;
            float4 v = make_float4(0.f, 0.f, 0.f, 0.f);
            if (n < N) {
                const float* wp = W + (size_t)n * K + k;
                if (k + 3 < K) v = *(const float4*)wp;
                else { if (k < K) v.x = wp[0]; if (k+1 < K) v.y = wp[1];
                       if (k+2 < K) v.z = wp[2]; if (k+3 < K) v.w = wp[3]; }
            }
            pfW = v;
        }

        // compute from current buffer
#pragma unroll
        for (int kk = 0; kk < 16; kk++) {
            unsigned long long a2[2];
            const unsigned long long* pa =
                (const unsigned long long*)&As[cur][kk][ty * 4];
            a2[0] = pa[0]; a2[1] = pa[1];
            float4 wv = *(const float4*)&Ws[cur][kk][tx * 4];
            unsigned long long w2[4];
            asm("mov.b64 %0, {%1, %2};" : "=l"(w2[0]) : "f"(wv.x), "f"(wv.x));
            asm("mov.b64 %0, {%1, %2};" : "=l"(w2[1]) : "f"(wv.y), "f"(wv.y));
            asm("mov.b64 %0, {%1, %2};" : "=l"(w2[2]) : "f"(wv.z), "f"(wv.z));
            asm("mov.b64 %0, {%1, %2};" : "=l"(w2[3]) : "f"(wv.w), "f"(wv.w));
#pragma unroll
            for (int p = 0; p < 2; p++)
#pragma unroll
                for (int j = 0; j < 4; j++)
                    asm("fma.rn.f32x2 %0, %1, %2, %0;"
                        : "+l"(acc[p][j]) : "l"(a2[p]), "l"(w2[j]));
        }

        // stage next tile into the other buffer
        if (more) {
#pragma unroll
            for (int i = 0; i < 2; i++) {
                int f = tid + i * 128;
                int m = f >> 2, kc = f & 3;
                As[nxt][kc*4+0][m] = pfA[i].x; As[nxt][kc*4+1][m] = pfA[i].y;
                As[nxt][kc*4+2][m] = pfA[i].z; As[nxt][kc*4+3][m] = pfA[i].w;
            }
            int n = tid >> 2, kc = tid & 3;
            Ws[nxt][kc*4+0][n] = pfW.x; Ws[nxt][kc*4+1][n] = pfW.y;
            Ws[nxt][kc*4+2][n] = pfW.z; Ws[nxt][kc*4+3][n] = pfW.w;
        }
        __syncthreads();
    }

    if (MODE == 2) {
        int n0 = bn + tx * 4;
        if (n0 >= N) return;
        int j = n0 >> 2;
        float bz[4];
#pragma unroll
        for (int g = 0; g < 4; g++) bz[g] = bias[n0 + g];
#pragma unroll
        for (int p = 0; p < 2; p++) {
            int m0 = bm + ty * 4 + 2 * p;
            float zl[4], zh[4];
#pragma unroll
            for (int g = 0; g < 4; g++) {
                float lo, hi;
                asm("mov.b64 {%0, %1}, %2;" : "=f"(lo), "=f"(hi) : "l"(acc[p][g]));
                zl[g] = lo + bz[g];
                zh[g] = hi + bz[g];
            }
#pragma unroll
            for (int r = 0; r < 2; r++) {
                int m = m0 + r;
                float zi = r ? zh[0] : zl[0];
                float zf = r ? zh[1] : zl[1];
                float zg = r ? zh[2] : zl[2];
                float zo = r ? zh[3] : zl[3];
                float c = g_c[m * H + j];
                float cn = sigf(zf) * c + sigf(zi) * tanhf(zg);
                float hn = sigf(zo) * tanhf(cn);
                g_c[m * H + j] = cn;
                g_h[m * H + j] = hn;
                g_Hbuf[((size_t)t * B + m) * H + j] = hn;
            }
        }
        return;
    }

    float bv[4];
#pragma unroll
    for (int j = 0; j < 4; j++) {
        int n = bn + tx * 4 + j;
        bv[j] = (bias && n < N) ? bias[n] : 0.f;
    }
#pragma unroll
    for (int p = 0; p < 2; p++) {
        int m0 = bm + ty * 4 + 2 * p;
#pragma unroll
        for (int j = 0; j < 4; j++) {
            int n = bn + tx * 4 + j;
            if (n >= N) continue;
            float lo, hi;
            asm("mov.b64 {%0, %1}, %2;" : "=f"(lo), "=f"(hi) : "l"(acc[p][j]));
            float v0 = lo + bv[j], v1 = hi + bv[j];
            if (MODE == 1) { v0 = tanhf(v0); v1 = tanhf(v1); }
            C[(size_t)m0 * N + n] = v0;
            C[(size_t)(m0 + 1) * N + n] = v1;
            if (MODE == 1) {
                C2[(size_t)m0 * XCAT + 32 + n] = v0;
                C2[(size_t)(m0 + 1) * XCAT + 32 + n] = v1;
            }
        }
    }
}

// ========== xw GEMM with fused embedding gather (prologue; R7-proven) ===========
__global__ void __launch_bounds__(256) k_xw(
    const int* __restrict__ sent, const float* __restrict__ src_emb,
    const float* __restrict__ Wf, const float* __restrict__ bf,
    const float* __restrict__ Wb, const float* __restrict__ bb)
{
    __shared__ float As[16][128];
    __shared__ float Ws[16][64];
    const int bm = blockIdx.y * 128, bn = blockIdx.x * 64;
    const float* W = blockIdx.z ? Wb : Wf;
    const float* bias = blockIdx.z ? bb : bf;
    float* C = blockIdx.z ? g_xw_b : g_xw_f;
    const int tid = threadIdx.x;
    const int ty = tid >> 4, tx = tid & 15;

    int sidx[2];
#pragma unroll
    for (int i = 0; i < 2; i++) {
        int f = tid + i * 256;
        sidx[i] = sent[bm + (f >> 2)];
    }

    float4 pfA[2], pfW;
#pragma unroll
    for (int i = 0; i < 2; i++) {
        int f = tid + i * 256;
        pfA[i] = *(const float4*)(src_emb + (size_t)sidx[i] * E + (f & 3) * 4);
    }
    {
        int n = bn + (tid >> 2), k = (tid & 3) * 4;
        pfW = (n < 400) ? *(const float4*)(W + (size_t)n * E + k)
                        : make_float4(0.f, 0.f, 0.f, 0.f);
    }

    unsigned long long acc[4][4];
#pragma unroll
    for (int p = 0; p < 4; p++)
#pragma unroll
        for (int j = 0; j < 4; j++) acc[p][j] = 0ull;

    for (int kt = 0; kt < 4; kt++) {
#pragma unroll
        for (int i = 0; i < 2; i++) {
            int f = tid + i * 256;
            int m = f >> 2, kc = f & 3;
            As[kc*4+0][m] = pfA[i].x; As[kc*4+1][m] = pfA[i].y;
            As[kc*4+2][m] = pfA[i].z; As[kc*4+3][m] = pfA[i].w;
        }
        { int n = tid >> 2, kc = tid & 3;
          Ws[kc*4+0][n] = pfW.x; Ws[kc*4+1][n] = pfW.y;
          Ws[kc*4+2][n] = pfW.z; Ws[kc*4+3][n] = pfW.w; }
        __syncthreads();

        if (kt + 1 < 4) {
            int k0 = (kt + 1) * 16;
#pragma unroll
            for (int i = 0; i < 2; i++) {
                int f = tid + i * 256;
                pfA[i] = *(const float4*)(src_emb + (size_t)sidx[i] * E + k0 + (f & 3) * 4);
            }
            int n = bn + (tid >> 2), k = k0 + (tid & 3) * 4;
            pfW = (n < 400) ? *(const float4*)(W + (size_t)n * E + k)
                            : make_float4(0.f, 0.f, 0.f, 0.f);
        }

#pragma unroll
        for (int kk = 0; kk < 16; kk++) {
            unsigned long long a2[4];
            const unsigned long long* pa = (const unsigned long long*)&As[kk][ty * 8];
#pragma unroll
            for (int p = 0; p < 4; p++) a2[p] = pa[p];
            float4 wv = *(const float4*)&Ws[kk][tx * 4];
            unsigned long long w2[4];
            asm("mov.b64 %0, {%1, %2};" : "=l"(w2[0]) : "f"(wv.x), "f"(wv.x));
            asm("mov.b64 %0, {%1, %2};" : "=l"(w2[1]) : "f"(wv.y), "f"(wv.y));
            asm("mov.b64 %0, {%1, %2};" : "=l"(w2[2]) : "f"(wv.z), "f"(wv.z));
            asm("mov.b64 %0, {%1, %2};" : "=l"(w2[3]) : "f"(wv.w), "f"(wv.w));
#pragma unroll
            for (int p = 0; p < 4; p++)
#pragma unroll
                for (int j = 0; j < 4; j++)
                    asm("fma.rn.f32x2 %0, %1, %2, %0;"
                        : "+l"(acc[p][j]) : "l"(a2[p]), "l"(w2[j]));
        }
        __syncthreads();
    }

    float bv[4];
#pragma unroll
    for (int j = 0; j < 4; j++) {
        int n = bn + tx * 4 + j;
        bv[j] = (n < 400) ? bias[n] : 0.f;
    }
#pragma unroll
    for (int p = 0; p < 4; p++) {
        int m0 = bm + ty * 8 + 2 * p;
#pragma unroll
        for (int j = 0; j < 4; j++) {
            int n = bn + tx * 4 + j;
            if (n >= 400) continue;
            float lo, hi;
            asm("mov.b64 {%0, %1}, %2;" : "=f"(lo), "=f"(hi) : "l"(acc[p][j]));
            C[(size_t)m0 * 400 + n] = lo + bv[j];
            C[(size_t)(m0 + 1) * 400 + n] = hi + bv[j];
        }
    }
}

// ---------------- fused bidirectional LSTM encoder (writes bf16 enc) ------------
#define ENC_BPB 14
#define ENC_SMEM_FLOATS (40000 + ENC_BPB * HH + ENC_BPB * 4 * HH)
__global__ void __launch_bounds__(256) k_encoder(const float* __restrict__ Whh_f,
                                                 const float* __restrict__ Whh_b)
{
    extern __shared__ float sm[];
    float* sW = sm;
    float* sh = sm + 40000;
    float* sz = sm + 40000 + ENC_BPB * HH;

    int dir = blockIdx.x >= 74;
    int lg = dir ? blockIdx.x - 74 : blockIdx.x;
    const float* Whh = dir ? Whh_b : Whh_f;
    const float* xw = dir ? g_xw_b : g_xw_f;
    float* cg = dir ? g_cb : g_cf;
    int b0 = lg * ENC_BPB;
    int nb = min(ENC_BPB, B - b0);
    int tid = threadIdx.x;

    for (int i = tid; i < 40000; i += 256) sW[i] = Whh[i];
    for (int i = tid; i < ENC_BPB * HH; i += 256) sh[i] = 0.f;
    float creg[6] = {0.f, 0.f, 0.f, 0.f, 0.f, 0.f};
    __syncthreads();

    for (int t = 0; t < S; t++) {
        int tt = dir ? (S - 1 - t) : t;
        if (tid < 200) {
            int jg = tid % 100;
            int bgb = (tid / 100) * 7;
            float acc[4][7];
#pragma unroll
            for (int r = 0; r < 4; r++)
#pragma unroll
                for (int bb = 0; bb < 7; bb++) {
                    int bl = bgb + bb;
                    acc[r][bb] = (bl < nb)
                        ? xw[((size_t)tt * B + (b0 + bl)) * 400 + 4 * jg + r] : 0.f;
                }
            const float4* shv = (const float4*)sh;
            const float4* swv = (const float4*)sW;
            for (int k4 = 0; k4 < 25; k4++) {
                float4 w0 = swv[(4 * jg + 0) * 25 + k4];
                float4 w1 = swv[(4 * jg + 1) * 25 + k4];
                float4 w2 = swv[(4 * jg + 2) * 25 + k4];
                float4 w3 = swv[(4 * jg + 3) * 25 + k4];
#pragma unroll
                for (int bb = 0; bb < 7; bb++) {
                    float4 hv = shv[(bgb + bb) * 25 + k4];
                    acc[0][bb] += w0.x * hv.x + w0.y * hv.y + w0.z * hv.z + w0.w * hv.w;
                    acc[1][bb] += w1.x * hv.x + w1.y * hv.y + w1.z * hv.z + w1.w * hv.w;
                    acc[2][bb] += w2.x * hv.x + w2.y * hv.y + w2.z * hv.z + w2.w * hv.w;
                    acc[3][bb] += w3.x * hv.x + w3.y * hv.y + w3.z * hv.z + w3.w * hv.w;
                }
            }
#pragma unroll
            for (int r = 0; r < 4; r++)
#pragma unroll
                for (int bb = 0; bb < 7; bb++)
                    if (bgb + bb < nb) sz[(bgb + bb) * 400 + 4 * jg + r] = acc[r][bb];
        }
        __syncthreads();
#pragma unroll
        for (int i = 0; i < 6; i++) {
            int pp = tid + i * 256;
            if (pp < nb * HH) {
                int bl = pp / HH, j = pp % HH;
                float zi = sz[bl * 400 + j];
                float zf = sz[bl * 400 + 100 + j];
                float zg = sz[bl * 400 + 200 + j];
                float zo = sz[bl * 400 + 300 + j];
                float cn = sigf(zf) * creg[i] + sigf(zi) * tanhf(zg);
                float hn = sigf(zo) * tanhf(cn);
                creg[i] = cn;
                sh[bl * HH + j] = hn;
                g_enc16[((size_t)(b0 + bl) * S + tt) * H + dir * HH + j] =
                    __float2bfloat16(hn);
            }
        }
        __syncthreads();
    }
#pragma unroll
    for (int i = 0; i < 6; i++) {
        int pp = tid + i * 256;
        if (pp < nb * HH) {
            int bl = pp / HH, j = pp % HH;
            cg[(b0 + bl) * HH + j] = creg[i];
            g_hfin[dir * B * HH + (b0 + bl) * HH + j] = sh[bl * HH + j];
        }
    }
}

// ---------------- weight prep: gate-interleaved Wcat/bcat + WattnT --------------
__global__ void k_prep(const float* __restrict__ Wih_d, const float* __restrict__ Whh_d,
                       const float* __restrict__ b_d, const float* __restrict__ W_attn) {
    int i = blockIdx.x * blockDim.x + threadIdx.x;
    if (i < 800 * XCAT) {
        int r = i / XCAT, k = i % XCAT;
        int src = (r & 3) * H + (r >> 2);
        g_Wcat[i] = (k < DEC_IN) ? Wih_d[src * DEC_IN + k]
                                 : Whh_d[src * H + (k - DEC_IN)];
    } else {
        int i2 = i - 800 * XCAT;
        if (i2 < H * H) {
            int k = i2 / H, j = i2 % H;
            g_WattnT[i2] = W_attn[j * H + k];
        } else {
            int r = i2 - H * H;
            if (r < 800) g_bcat[r] = b_d[(r & 3) * H + (r >> 2)];
        }
    }
}

// ---------------- decoder init: h0/c0 + initial xcat (inp=0 | h0) ---------------
__global__ void k_dec_init2() {
    int e = blockIdx.x * blockDim.x + threadIdx.x;
    if (e >= B * XCAT) return;
    int b = e / XCAT, col = e % XCAT;
    if (col < DEC_IN) { g_xcat[e] = 0.f; return; }
    int k = col - DEC_IN;
    int hi = (k >= HH) ? 1 : 0;
    int j = k - hi * HH;
    float hv, cv;
    if (b < 512) {
        int bb = 2 * b + hi;
        hv = g_hfin[bb * HH + j];
        cv = g_cf[bb * HH + j];
    } else {
        int bb = 2 * (b - 512) + hi;
        hv = g_hfin[B * HH + bb * HH + j];
        cv = g_cb[bb * HH + j];
    }
    g_h[b * H + k] = hv;
    g_c[b * H + k] = cv;
    g_xcat[e] = hv;
}

// ---------------- attention: online softmax over bf16 enc (R13-proven) ----------
__global__ void __launch_bounds__(256) k_attn2(
    int t, const int* __restrict__ is_prod, const int* __restrict__ prod_ids,
    const int* __restrict__ prim_ids, const int* __restrict__ field_ids,
    const int* __restrict__ parent_t,
    const float* __restrict__ actprod, const float* __restrict__ prim,
    const float* __restrict__ field)
{
    cudaGridDependencySynchronize();
    __shared__ float sg[H];
    __shared__ float wm[8], ws[8];
    __shared__ float wctx[8][H];
    int b = blockIdx.x, tid = threadIdx.x;
    int warp = tid >> 5, lane = tid & 31;

    if (tid < H) sg[tid] = g_gtil[b * H + tid];
    __syncthreads();

    float sgr[8];
#pragma unroll
    for (int i = 0; i < 4; i++) {
        int k2 = lane + 32 * i;
        sgr[2*i]   = (k2 < 100) ? sg[2*k2]   : 0.f;
        sgr[2*i+1] = (k2 < 100) ? sg[2*k2+1] : 0.f;
    }

    float m = -1e30f, zsum = 0.f;
    float ctx[8] = {0.f, 0.f, 0.f, 0.f, 0.f, 0.f, 0.f, 0.f};
    const __nv_bfloat162* eb =
        (const __nv_bfloat162*)(g_enc16 + (size_t)b * S * H);
#pragma unroll 2
    for (int si = 0; si < 16; si++) {
        int s = warp * 16 + si;
        const __nv_bfloat162* er = eb + s * 100;
        float v[8];
#pragma unroll
        for (int i = 0; i < 4; i++) {
            int k2 = lane + 32 * i;
            if (k2 < 100) {
                float2 p = __bfloat1622float2(er[k2]);
                v[2*i] = p.x; v[2*i+1] = p.y;
            } else { v[2*i] = 0.f; v[2*i+1] = 0.f; }
        }
        float sc = 0.f;
#pragma unroll
        for (int i = 0; i < 8; i++) sc += v[i] * sgr[i];
#pragma unroll
        for (int o = 16; o; o >>= 1) sc += __shfl_xor_sync(0xffffffffu, sc, o);
        float mn = fmaxf(m, sc);
        float corr = expf(m - mn);
        float e = expf(sc - mn);
        zsum = zsum * corr + e;
#pragma unroll
        for (int i = 0; i < 8; i++) ctx[i] = ctx[i] * corr + e * v[i];
        m = mn;
    }
    if (lane == 0) { wm[warp] = m; ws[warp] = zsum; }
#pragma unroll
    for (int i = 0; i < 4; i++) {
        int k2 = lane + 32 * i;
        if (k2 < 100) {
            wctx[warp][2*k2]   = ctx[2*i];
            wctx[warp][2*k2+1] = ctx[2*i+1];
        }
    }
    __syncthreads();

    float M = wm[0];
#pragma unroll
    for (int w = 1; w < 8; w++) M = fmaxf(M, wm[w]);
    float Z = 0.f;
#pragma unroll
    for (int w = 0; w < 8; w++) Z = fmaf(ws[w], expf(wm[w] - M), Z);
    float invZ = 1.f / Z;
    if (tid < H) {
        float cx = 0.f;
#pragma unroll
        for (int w = 0; w < 8; w++) cx = fmaf(wctx[w][tid], expf(wm[w] - M), cx);
        cx *= invZ;
        g_cath[b * 2 * H + tid] = cx;
        g_cath[b * 2 * H + H + tid] = g_h[b * H + tid];
    }

    int t1 = t + 1;
    if (t1 >= T) return;
    for (int cc = tid; cc < 440; cc += 256) {
        int col;
        float v;
        if (cc < 32) {
            col = cc;
            int idx = t1 * B + b;
            v = (is_prod[idx] == 1) ? actprod[prod_ids[idx] * 32 + cc]
                                    : prim[prim_ids[idx] * 32 + cc];
        } else if (cc < 40) {
            col = 232 + (cc - 32);
            v = field[field_ids[t1 * B + b] * 8 + (cc - 32)];
        } else if (cc < 240) {
            int j = cc - 40;
            col = 240 + j;
            int pt = parent_t[t1 * B + b];
            v = g_Hbuf[((size_t)pt * B + b) * H + j];
        } else {
            int j = cc - 240;
            col = DEC_IN + j;
            v = g_h[b * H + j];
        }
        g_xcat[(size_t)b * XCAT + col] = v;
    }
}

// ---------------- host launch ----------------
extern "C" void kernel_launch(void* const* d_in, const int* in_sizes, int n_in,
                              void* d_out, int out_size) {
    const int* sentences  = (const int*)d_in[0];
    const int* is_prod    = (const int*)d_in[1];
    const int* prod_ids   = (const int*)d_in[2];
    const int* prim_ids   = (const int*)d_in[3];
    const int* field_ids  = (const int*)d_in[4];
    const int* parent_t   = (const int*)d_in[5];
    const float* src_emb  = (const float*)d_in[6];
    const float* actprod_emb = (const float*)d_in[7];
    const float* prim_emb = (const float*)d_in[8];
    const float* field_emb = (const float*)d_in[9];
    const float* Wih_f = (const float*)d_in[10];
    const float* Whh_f = (const float*)d_in[11];
    const float* b_f   = (const float*)d_in[12];
    const float* Wih_b = (const float*)d_in[13];
    const float* Whh_b = (const float*)d_in[14];
    const float* b_b   = (const float*)d_in[15];
    const float* Wih_d = (const float*)d_in[16];
    const float* Whh_d = (const float*)d_in[17];
    const float* b_d   = (const float*)d_in[18];
    const float* W_attn = (const float*)d_in[19];
    const float* W_av   = (const float*)d_in[20];
    float* out = (float*)d_out;

    void *p_xcat, *p_Wcat, *p_bcat, *p_h, *p_WaT, *p_gtil, *p_cath;
    cudaGetSymbolAddress(&p_xcat, g_xcat);
    cudaGetSymbolAddress(&p_Wcat, g_Wcat);
    cudaGetSymbolAddress(&p_bcat, g_bcat);
    cudaGetSymbolAddress(&p_h, g_h);
    cudaGetSymbolAddress(&p_WaT, g_WattnT);
    cudaGetSymbolAddress(&p_gtil, g_gtil);
    cudaGetSymbolAddress(&p_cath, g_cath);

    cudaFuncSetAttribute(k_encoder, cudaFuncAttributeMaxDynamicSharedMemorySize,
                         ENC_SMEM_FLOATS * 4);

    cudaLaunchAttribute at[1];
    at[0].id = cudaLaunchAttributeProgrammaticStreamSerialization;
    at[0].val.programmaticStreamSerializationAllowed = 1;

    // 1) xw projections with fused embedding gather (both directions)
    {
        dim3 g(7, (S * B) / 128, 2);
        k_xw<<<g, 256>>>(sentences, src_emb, Wih_f, b_f, Wih_b, b_b);
    }
    // 2) bidirectional encoder (writes bf16 g_enc16 directly)
    k_encoder<<<148, 256, ENC_SMEM_FLOATS * 4>>>(Whh_f, Whh_b);
    // 3) weight prep + decoder init
    k_prep<<<(800 * XCAT + H * H + 800 + 255) / 256, 256>>>(Wih_d, Whh_d, b_d, W_attn);
    k_dec_init2<<<(B * XCAT + 255) / 256, 256>>>();

    // 4) decoder loop: 4 PDL-chained nodes; 64x32 tiles (R11/R13-proven)
    dim3 gz(25, 16);   // zcell: 400 blocks
    dim3 gs(7, 16);    // gtil/out: 112 blocks
    for (int t = 0; t < T; t++) {
        {
            cudaLaunchConfig_t cfg = {};
            cfg.gridDim = gz; cfg.blockDim = dim3(128);
            cfg.attrs = at; cfg.numAttrs = 1;
            cudaLaunchKernelEx(&cfg, k_gemm<2>,
                (const float*)p_xcat, (const float*)p_Wcat, (const float*)p_bcat,
                (float*)nullptr, (float*)nullptr, (int)B, (int)(4 * H), (int)XCAT, t);
        }
        {
            cudaLaunchConfig_t cfg = {};
            cfg.gridDim = gs; cfg.blockDim = dim3(128);
            cfg.attrs = at; cfg.numAttrs = 1;
            cudaLaunchKernelEx(&cfg, k_gemm<0>,
                (const float*)p_h, (const float*)p_WaT, (const float*)nullptr,
                (float*)p_gtil, (float*)nullptr, (int)B, (int)H, (int)H, 0);
        }
        {
            cudaLaunchConfig_t cfg = {};
            cfg.gridDim = dim3(B); cfg.blockDim = dim3(256);
            cfg.attrs = at; cfg.numAttrs = 1;
            cudaLaunchKernelEx(&cfg, k_attn2, t, is_prod, prod_ids, prim_ids,
                               field_ids, parent_t, actprod_emb, prim_emb, field_emb);
        }
        {
            cudaLaunchConfig_t cfg = {};
            cfg.gridDim = gs; cfg.blockDim = dim3(128);
            cfg.attrs = at; cfg.numAttrs = 1;
            cudaLaunchKernelEx(&cfg, k_gemm<1>,
                (const float*)p_cath, W_av, (const float*)nullptr,
                out + (size_t)t * B * ATT, (float*)p_xcat,
                (int)B, (int)ATT, (int)(2 * H), 0);
        }
    }
}